// round 2
// baseline (speedup 1.0000x reference)
#include <cuda_runtime.h>
#include <math.h>

#define BATCH 8
#define SEQ   2048
#define EMB   1024
#define HEAD  128
#define NTRI  136            // 16*17/2 lower-triangular 128x128 tiles per batch
#define SCALE 0.03125f       // 1/sqrt(1024)

// ---------------- scratch (__device__ globals: allocation-free) ----------------
__device__ float g_q[BATCH * SEQ * HEAD];
__device__ float g_k[BATCH * SEQ * HEAD];
__device__ float g_v[BATCH * SEQ * HEAD];
__device__ float g_expS[(size_t)BATCH * SEQ * SEQ];   // 128 MB
__device__ float g_colsum[BATCH * SEQ];
__device__ float g_colinv[BATCH * SEQ];

// ---------------- fast exp: FMA-pipe polynomial (scores are small) -------------
// degree-12 Taylor, Horner form. |err| < ~1e-5 for |x| <= 2. Rare fallback branch.
__device__ __forceinline__ float fast_exp(float x) {
    float r = 2.0876757e-9f;              // 1/12!
    r = fmaf(r, x, 2.5052108e-8f);        // 1/11!
    r = fmaf(r, x, 2.7557319e-7f);        // 1/10!
    r = fmaf(r, x, 2.7557319e-6f);        // 1/9!
    r = fmaf(r, x, 2.4801587e-5f);        // 1/8!
    r = fmaf(r, x, 1.9841270e-4f);        // 1/7!
    r = fmaf(r, x, 1.3888889e-3f);        // 1/6!
    r = fmaf(r, x, 8.3333333e-3f);        // 1/5!
    r = fmaf(r, x, 4.1666667e-2f);        // 1/4!
    r = fmaf(r, x, 1.6666667e-1f);        // 1/3!
    r = fmaf(r, x, 0.5f);                 // 1/2!
    r = fmaf(r, x, 1.0f);                 // 1/1!
    r = fmaf(r, x, 1.0f);                 // 1/0!
    if (fabsf(x) > 2.0f) r = __expf(x);   // branch, almost never taken
    return r;
}

__device__ __forceinline__ void tri_decode(int t, int& qt, int& kt) {
    int q = (int)((sqrtf(8.0f * (float)t + 1.0f) - 1.0f) * 0.5f);
    while ((q + 1) * (q + 2) / 2 <= t) q++;
    while (q * (q + 1) / 2 > t) q--;
    qt = q;
    kt = t - q * (q + 1) / 2;
}

// ---------------- kernel 0: zero output + column sums --------------------------
__global__ void zero_kernel(float* __restrict__ out) {
    int i = blockIdx.x * blockDim.x + threadIdx.x;
    if (i < BATCH * SEQ * HEAD) out[i] = 0.0f;
    if (i < BATCH * SEQ) g_colsum[i] = 0.0f;
}

// ---------------- kernel 1: QKV projection ------------------------------------
// Y = X @ W, X:[16384,1024], W:[1024,128]. blockIdx.z selects Wq/Wk/Wv.
// 128x128 block tile, BK=8, 256 threads, 8x8 microtile.
__global__ __launch_bounds__(256, 2) void qkv_kernel(
    const float* __restrict__ X, const float* __restrict__ Wq,
    const float* __restrict__ Wk, const float* __restrict__ Wv) {
    const float* W = (blockIdx.z == 0) ? Wq : (blockIdx.z == 1) ? Wk : Wv;
    float* Y       = (blockIdx.z == 0) ? g_q : (blockIdx.z == 1) ? g_k : g_v;

    __shared__ float As[8][132];   // padded: conflict-free transposed stores
    __shared__ float Bs[8][128];

    const int tid  = threadIdx.x;
    const int tx   = tid & 15, ty = tid >> 4;
    const int arow = tid >> 1, ac4 = (tid & 1) * 4;
    const int brow = tid >> 5, bc4 = (tid & 31) * 4;
    const int rowBase = blockIdx.x * 128;

    float acc[8][8];
#pragma unroll
    for (int i = 0; i < 8; i++)
#pragma unroll
        for (int j = 0; j < 8; j++) acc[i][j] = 0.0f;

    const float* Xp = X + (size_t)(rowBase + arow) * EMB + ac4;

    for (int k0 = 0; k0 < EMB; k0 += 8) {
        float4 av = *(const float4*)(Xp + k0);
        float4 bv = *(const float4*)(W + (size_t)(k0 + brow) * HEAD + bc4);
        __syncthreads();
        As[ac4 + 0][arow] = av.x; As[ac4 + 1][arow] = av.y;
        As[ac4 + 2][arow] = av.z; As[ac4 + 3][arow] = av.w;
        *(float4*)&Bs[brow][bc4] = bv;
        __syncthreads();
#pragma unroll
        for (int kk = 0; kk < 8; kk++) {
            float a[8], b[8];
#pragma unroll
            for (int i = 0; i < 8; i++) a[i] = As[kk][ty * 8 + i];
#pragma unroll
            for (int j = 0; j < 8; j++) b[j] = Bs[kk][tx * 8 + j];
#pragma unroll
            for (int i = 0; i < 8; i++)
#pragma unroll
                for (int j = 0; j < 8; j++)
                    acc[i][j] = fmaf(a[i], b[j], acc[i][j]);
        }
    }
#pragma unroll
    for (int i = 0; i < 8; i++) {
        float* yp = Y + (size_t)(rowBase + ty * 8 + i) * HEAD + tx * 8;
        *(float4*)yp       = make_float4(acc[i][0], acc[i][1], acc[i][2], acc[i][3]);
        *(float4*)(yp + 4) = make_float4(acc[i][4], acc[i][5], acc[i][6], acc[i][7]);
    }
}

// ---------------- kernel 2: scores (lower-tri tiles only) ----------------------
// S = q kT / 32 ; expS stored ; per-key-column sums via shared + global atomics.
__global__ __launch_bounds__(256, 2) void scores_kernel() {
    const int b = blockIdx.x / NTRI;
    int qt, kt;
    tri_decode(blockIdx.x % NTRI, qt, kt);

    __shared__ float As[8][132];
    __shared__ float Bs[8][132];
    __shared__ float s_col[128];

    const int tid  = threadIdx.x;
    const int tx   = tid & 15, ty = tid >> 4;
    const int lrow = tid >> 1, lc4 = (tid & 1) * 4;

    const float* qp = g_q + ((size_t)b * SEQ + qt * 128 + lrow) * HEAD + lc4;
    const float* kp = g_k + ((size_t)b * SEQ + kt * 128 + lrow) * HEAD + lc4;

    float acc[8][8];
#pragma unroll
    for (int i = 0; i < 8; i++)
#pragma unroll
        for (int j = 0; j < 8; j++) acc[i][j] = 0.0f;

    for (int h0 = 0; h0 < HEAD; h0 += 8) {
        float4 av = *(const float4*)(qp + h0);
        float4 bv = *(const float4*)(kp + h0);
        __syncthreads();
        As[lc4 + 0][lrow] = av.x; As[lc4 + 1][lrow] = av.y;
        As[lc4 + 2][lrow] = av.z; As[lc4 + 3][lrow] = av.w;
        Bs[lc4 + 0][lrow] = bv.x; Bs[lc4 + 1][lrow] = bv.y;
        Bs[lc4 + 2][lrow] = bv.z; Bs[lc4 + 3][lrow] = bv.w;
        __syncthreads();
#pragma unroll
        for (int kk = 0; kk < 8; kk++) {
            float a[8], bb[8];
#pragma unroll
            for (int i = 0; i < 8; i++) a[i] = As[kk][ty * 8 + i];
#pragma unroll
            for (int j = 0; j < 8; j++) bb[j] = Bs[kk][tx * 8 + j];
#pragma unroll
            for (int i = 0; i < 8; i++)
#pragma unroll
                for (int j = 0; j < 8; j++)
                    acc[i][j] = fmaf(a[i], bb[j], acc[i][j]);
        }
    }

    if (tid < 128) s_col[tid] = 0.0f;
    __syncthreads();

    float colpart[8];
#pragma unroll
    for (int j = 0; j < 8; j++) colpart[j] = 0.0f;

    const int r0 = qt * 128 + ty * 8;
    const int c0 = kt * 128 + tx * 8;
#pragma unroll
    for (int i = 0; i < 8; i++) {
        float e[8];
#pragma unroll
        for (int j = 0; j < 8; j++) {
            float s  = acc[i][j] * SCALE;
            float ev = 0.0f;
            if (r0 + i >= c0 + j) ev = fast_exp(s);   // causal: keep q >= k
            e[j] = ev;
            colpart[j] += ev;
        }
        float* ep = g_expS + ((size_t)b * SEQ + (size_t)(r0 + i)) * SEQ + c0;
        *(float4*)ep       = make_float4(e[0], e[1], e[2], e[3]);
        *(float4*)(ep + 4) = make_float4(e[4], e[5], e[6], e[7]);
    }
#pragma unroll
    for (int j = 0; j < 8; j++) atomicAdd(&s_col[tx * 8 + j], colpart[j]);
    __syncthreads();
    if (tid < 128) atomicAdd(&g_colsum[b * SEQ + kt * 128 + tid], s_col[tid]);
}

// ---------------- kernel 3: reciprocal of column sums --------------------------
__global__ void colinv_kernel() {
    int i = blockIdx.x * blockDim.x + threadIdx.x;
    if (i < BATCH * SEQ) g_colinv[i] = 1.0f / g_colsum[i];
}

// ---------------- kernel 4: out = (expS * colinv) @ v (lower-tri tiles) --------
__global__ __launch_bounds__(256, 2) void out_kernel(float* __restrict__ out) {
    const int b = blockIdx.x / NTRI;
    int qt, kt;
    tri_decode(blockIdx.x % NTRI, qt, kt);

    __shared__ float As[8][132];
    __shared__ float Bs[8][128];
    __shared__ float s_inv[128];

    const int tid = threadIdx.x;
    if (tid < 128) s_inv[tid] = g_colinv[b * SEQ + kt * 128 + tid];

    const int tx   = tid & 15, ty = tid >> 4;
    const int arow = tid >> 1, ac4 = (tid & 1) * 4;
    const int brow = tid >> 5, bc4 = (tid & 31) * 4;

    const float* Ap = g_expS + ((size_t)b * SEQ + qt * 128 + arow) * SEQ + kt * 128 + ac4;
    const float* Vp = g_v + ((size_t)b * SEQ + kt * 128 + brow) * HEAD + bc4;

    float acc[8][8];
#pragma unroll
    for (int i = 0; i < 8; i++)
#pragma unroll
        for (int j = 0; j < 8; j++) acc[i][j] = 0.0f;

    for (int k0 = 0; k0 < 128; k0 += 8) {
        float4 av = *(const float4*)(Ap + k0);
        float4 bv = *(const float4*)(Vp + (size_t)k0 * HEAD);
        __syncthreads();   // also orders s_inv store before first use
        As[ac4 + 0][arow] = av.x * s_inv[k0 + ac4 + 0];
        As[ac4 + 1][arow] = av.y * s_inv[k0 + ac4 + 1];
        As[ac4 + 2][arow] = av.z * s_inv[k0 + ac4 + 2];
        As[ac4 + 3][arow] = av.w * s_inv[k0 + ac4 + 3];
        *(float4*)&Bs[brow][bc4] = bv;
        __syncthreads();
#pragma unroll
        for (int kk = 0; kk < 8; kk++) {
            float a[8], bb[8];
#pragma unroll
            for (int i = 0; i < 8; i++) a[i] = As[kk][ty * 8 + i];
#pragma unroll
            for (int j = 0; j < 8; j++) bb[j] = Bs[kk][tx * 8 + j];
#pragma unroll
            for (int i = 0; i < 8; i++)
#pragma unroll
                for (int j = 0; j < 8; j++)
                    acc[i][j] = fmaf(a[i], bb[j], acc[i][j]);
        }
    }
#pragma unroll
    for (int i = 0; i < 8; i++)
#pragma unroll
        for (int j = 0; j < 8; j++)
            atomicAdd(&out[((size_t)b * SEQ + qt * 128 + ty * 8 + i) * HEAD + tx * 8 + j],
                      acc[i][j]);
}

// ---------------- launch --------------------------------------------------------
extern "C" void kernel_launch(void* const* d_in, const int* in_sizes, int n_in,
                              void* d_out, int out_size) {
    const float* X  = (const float*)d_in[0];
    const float* Wq = (const float*)d_in[1];
    const float* Wk = (const float*)d_in[2];
    const float* Wv = (const float*)d_in[3];
    float* out = (float*)d_out;

    zero_kernel<<<(BATCH * SEQ * HEAD + 255) / 256, 256>>>(out);
    qkv_kernel<<<dim3(BATCH * SEQ / 128, 1, 3), 256>>>(X, Wq, Wk, Wv);
    scores_kernel<<<BATCH * NTRI, 256>>>();
    colinv_kernel<<<(BATCH * SEQ + 255) / 256, 256>>>();
    out_kernel<<<BATCH * NTRI, 256>>>(out);
}